// round 15
// baseline (speedup 1.0000x reference)
#include <cuda_runtime.h>
#include <cuda_bf16.h>
#include <math.h>
#include <stdint.h>

// ---------------------------------------------------------------------------
// ManifoldTransformer on GB300 via mma.sync bf16 (fp32 accumulate).
// 3-term hi/lo split along K (exact fp32-class):
//   A stream per k: (Ah, Al, Ah) ; B stream per k: (Bh, Bh, Bl)
//   -> Ah*Bh + Al*Bh + Ah*Bl  (dropped Al*Bl ~ 4e-6 relative)
// NEW: all GEMM operands pre-split in gmem (weights via wsplit3 kernels,
// activations in producer epilogues), GEMM loads are pure cp.async 3-stage
// pipeline -> global latency off the critical path.
// Attention: HMMA flash (R8 champion compute), triple-bf16 output.
// B=2,S=1024,D=512,H=8,DFF=2048,L=4,V=50257.
// ---------------------------------------------------------------------------

#define NROWS 2048
#define DMODEL 512
#define DFF 2048
#define NLAYER 4
#define VOCAB 50257
#define SEQ 1024
#define QKV_LD 1536

#define K3_D (3 * DMODEL)    // 1536
#define K3_F (3 * DFF)       // 6144

// ---------------- scratch (device globals: allocation-free) -----------------
__device__ __align__(256) float g_x  [NROWS * DMODEL];
__device__ __align__(256) float g_qkv[NROWS * QKV_LD];
__device__ __align__(256) float g_bqkv[NLAYER * QKV_LD];
__device__ __align__(256) __nv_bfloat16 g_h3 [NROWS * K3_D];
__device__ __align__(256) __nv_bfloat16 g_ao3[NROWS * K3_D];
__device__ __align__(256) __nv_bfloat16 g_ff3[NROWS * K3_F];
// pre-split weights, (h,h,l) along K3
__device__ __align__(256) __nv_bfloat16 g_wqkv3[NLAYER * QKV_LD * K3_D];
__device__ __align__(256) __nv_bfloat16 g_wo3  [NLAYER * DMODEL * K3_D];
__device__ __align__(256) __nv_bfloat16 g_w13  [NLAYER * DFF    * K3_D];
__device__ __align__(256) __nv_bfloat16 g_w23  [NLAYER * DMODEL * K3_F];
__device__ __align__(256) __nv_bfloat16 g_wh3  [(size_t)VOCAB   * K3_D];

// ---------------- helpers ----------------------------------------------------
__device__ __forceinline__ uint32_t smem_u32(const void* p) {
    uint32_t a;
    asm("{ .reg .u64 t; cvta.to.shared.u64 t, %1; cvt.u32.u64 %0, t; }"
        : "=r"(a) : "l"(p));
    return a;
}
__device__ __forceinline__ void ldsm4(uint32_t* r, uint32_t addr) {
    asm volatile("ldmatrix.sync.aligned.m8n8.x4.shared.b16 {%0,%1,%2,%3}, [%4];"
        : "=r"(r[0]), "=r"(r[1]), "=r"(r[2]), "=r"(r[3]) : "r"(addr));
}
__device__ __forceinline__ void mma16816(float* d, const uint32_t* a, const uint32_t* b) {
    asm volatile("mma.sync.aligned.m16n8k16.row.col.f32.bf16.bf16.f32 "
        "{%0,%1,%2,%3}, {%4,%5,%6,%7}, {%8,%9}, {%0,%1,%2,%3};"
        : "+f"(d[0]), "+f"(d[1]), "+f"(d[2]), "+f"(d[3])
        : "r"(a[0]), "r"(a[1]), "r"(a[2]), "r"(a[3]), "r"(b[0]), "r"(b[1]));
}
__device__ __forceinline__ __nv_bfloat162 split1(float x) {
    __nv_bfloat162 r;
    r.x = __float2bfloat16(x);
    r.y = __float2bfloat16(x - __bfloat162float(r.x));
    return r;
}
__device__ __forceinline__ uint32_t pack2(__nv_bfloat16 a, __nv_bfloat16 b) {
    __nv_bfloat162 t; t.x = a; t.y = b;
    return *(uint32_t*)&t;
}
__device__ __forceinline__ void cpasync16(uint32_t daddr, const void* src, uint32_t sz) {
    asm volatile("cp.async.ca.shared.global [%0], [%1], 16, %2;"
        :: "r"(daddr), "l"(src), "r"(sz) : "memory");
}
#define CP_COMMIT() asm volatile("cp.async.commit_group;" ::: "memory")
#define CP_WAIT1()  asm volatile("cp.async.wait_group 1;" ::: "memory")

// ---------------- weight split: per element emit (h, h, l) ------------------
__global__ void wsplit3_kernel(const float* __restrict__ src,
                               __nv_bfloat16* __restrict__ dst, long n8)
{
    long i = (long)blockIdx.x * 256 + threadIdx.x;
    if (i >= n8) return;
    float4 v0 = *(const float4*)(src + i * 8);
    float4 v1 = *(const float4*)(src + i * 8 + 4);
    union { __nv_bfloat16 h[24]; uint4 u[3]; } P;
    const float vv[8] = {v0.x, v0.y, v0.z, v0.w, v1.x, v1.y, v1.z, v1.w};
    #pragma unroll
    for (int e = 0; e < 8; e++) {
        __nv_bfloat162 s = split1(vv[e]);
        P.h[e * 3 + 0] = s.x;
        P.h[e * 3 + 1] = s.x;
        P.h[e * 3 + 2] = s.y;
    }
    uint4* q = (uint4*)(dst + i * 24);
    q[0] = P.u[0]; q[1] = P.u[1]; q[2] = P.u[2];
}

// ---------------- embedding -------------------------------------------------
__global__ void embed_kernel(const int* __restrict__ tok,
                             const float* __restrict__ emb,
                             const float* __restrict__ pos,
                             float* __restrict__ x)
{
    int row = blockIdx.x, tid = threadIdx.x;
    int t = tok[row], s = row & (SEQ - 1);
    float4 e = *(const float4*)&emb[(size_t)t * DMODEL + tid * 4];
    float4 p = *(const float4*)&pos[(size_t)s * DMODEL + tid * 4];
    e.x += p.x; e.y += p.y; e.z += p.z; e.w += p.w;
    *(float4*)&x[(size_t)row * DMODEL + tid * 4] = e;
}

// ---------------- LayerNorm -> triple bf16 (h,l,h) ---------------------------
__global__ void ln_kernel(const float* __restrict__ x,
                          const float* __restrict__ g,
                          const float* __restrict__ b,
                          __nv_bfloat16* __restrict__ y3)
{
    __shared__ float red[4];
    __shared__ float bc;
    int row = blockIdx.x, tid = threadIdx.x;
    int lane = tid & 31, w = tid >> 5;

    float4 v = *(const float4*)&x[(size_t)row * DMODEL + tid * 4];
    float s = v.x + v.y + v.z + v.w;
    #pragma unroll
    for (int o = 16; o; o >>= 1) s += __shfl_xor_sync(0xffffffffu, s, o);
    if (lane == 0) red[w] = s;
    __syncthreads();
    if (tid == 0) bc = (red[0] + red[1] + red[2] + red[3]) * (1.0f / 512.0f);
    __syncthreads();
    float mean = bc;
    float dx = v.x - mean, dy = v.y - mean, dz = v.z - mean, dw = v.w - mean;
    float s2 = dx*dx + dy*dy + dz*dz + dw*dw;
    #pragma unroll
    for (int o = 16; o; o >>= 1) s2 += __shfl_xor_sync(0xffffffffu, s2, o);
    __syncthreads();
    if (lane == 0) red[w] = s2;
    __syncthreads();
    if (tid == 0) bc = rsqrtf((red[0] + red[1] + red[2] + red[3]) * (1.0f / 512.0f) + 1e-5f);
    __syncthreads();
    float inv = bc;

    float4 gg = *(const float4*)&g[tid * 4];
    float4 bb = *(const float4*)&b[tid * 4];
    float ov[4];
    ov[0] = dx * inv * gg.x + bb.x;
    ov[1] = dy * inv * gg.y + bb.y;
    ov[2] = dz * inv * gg.z + bb.z;
    ov[3] = dw * inv * gg.w + bb.w;
    union { __nv_bfloat16 h[12]; uint2 u[3]; } P;
    #pragma unroll
    for (int e = 0; e < 4; e++) {
        __nv_bfloat162 sp = split1(ov[e]);
        P.h[e * 3 + 0] = sp.x;
        P.h[e * 3 + 1] = sp.y;
        P.h[e * 3 + 2] = sp.x;
    }
    uint2* q = (uint2*)(y3 + (size_t)row * K3_D + tid * 12);
    q[0] = P.u[0]; q[1] = P.u[1]; q[2] = P.u[2];
}

// ---------------------------------------------------------------------------
// HMMA GEMM, both operands pre-split triple bf16, cp.async 3-stage pipeline.
// C[M,N] = A3[M,K3] @ B3[N,K3]^T. CTA 128x128 over K3 chunks of 48.
// 256 threads: tid<128 loads A row tid, tid>=128 loads B row tid-128
// (6x cp.async 16B each). 8 warps each 32x64 compute.
// ---------------------------------------------------------------------------
#define SROW 112
#define TILE (128 * SROW)
#define STAGE (2 * TILE)
#define GSMEM (3 * STAGE)

template<bool GELU, bool RES, bool TRIPLEOUT, bool SWAP>
__global__ __launch_bounds__(256, 2)
void hmma_gemm(const __nv_bfloat16* __restrict__ A3, const __nv_bfloat16* __restrict__ B3,
               const float* __restrict__ bias, const float* __restrict__ Rres,
               void* __restrict__ Cout, int N, int K3, int ldc)
{
    extern __shared__ __align__(16) char sm[];
    const uint32_t smbase = smem_u32(sm);

    const int tid = threadIdx.x;
    const int lane = tid & 31, wid = tid >> 5;
    const int wm = wid & 3, wn = wid >> 2;
    const int m0 = (SWAP ? blockIdx.x : blockIdx.y) << 7;
    const int n0 = (SWAP ? blockIdx.y : blockIdx.x) << 7;

    // loader mapping
    const int lrow = tid & 127, lside = tid >> 7;
    const __nv_bfloat16* gsrc;
    uint32_t csz;
    if (lside == 0) {
        gsrc = A3 + (size_t)(m0 + lrow) * K3;
        csz = 16u;
    } else {
        bool valid = (n0 + lrow < N);
        gsrc = B3 + (valid ? (size_t)(n0 + lrow) * K3 : 0);
        csz = valid ? 16u : 0u;
    }
    const uint32_t sdst0 = smbase + lside * TILE + lrow * SROW;

    float acc[2][8][4];
    #pragma unroll
    for (int i = 0; i < 2; i++)
        #pragma unroll
        for (int j = 0; j < 8; j++)
            #pragma unroll
            for (int k = 0; k < 4; k++) acc[i][j][k] = 0.0f;

    const int nc = K3 / 48;

    auto issue = [&](int c) {
        uint32_t dst = sdst0 + (c % 3) * STAGE;
        const char* src = (const char*)gsrc + (size_t)c * 96;
        #pragma unroll
        for (int i = 0; i < 6; i++) cpasync16(dst + i * 16, src + i * 16, csz);
    };
    auto compute = [&](int stage) {
        uint32_t aBase = smbase + stage * STAGE;
        uint32_t bBase = aBase + TILE;
        #pragma unroll
        for (int ks = 0; ks < 3; ks++) {
            uint32_t afrag[2][4];
            #pragma unroll
            for (int mi = 0; mi < 2; mi++) {
                int arow = wm * 32 + mi * 16 + (lane & 15);
                int abyte = ks * 32 + ((lane >> 4) << 4);
                ldsm4(afrag[mi], aBase + arow * SROW + abyte);
            }
            uint32_t bfrag[4][4];
            #pragma unroll
            for (int ni = 0; ni < 4; ni++) {
                int brow = wn * 64 + ni * 16 + (lane & 7) + ((lane >> 4) << 3);
                int bbyte = ks * 32 + (((lane >> 3) & 1) << 4);
                ldsm4(bfrag[ni], bBase + brow * SROW + bbyte);
            }
            #pragma unroll
            for (int mi = 0; mi < 2; mi++)
                #pragma unroll
                for (int t = 0; t < 8; t++)
                    mma16816(acc[mi][t], afrag[mi], &bfrag[t >> 1][(t & 1) * 2]);
        }
    };

    issue(0); CP_COMMIT();
    issue(1); CP_COMMIT();
    for (int c = 0; c < nc; c++) {
        CP_WAIT1();            // group c complete (invariant: newest committed = c+1)
        __syncthreads();       // stage c visible; stage (c+2)%3 fully consumed
        if (c + 2 < nc) issue(c + 2);
        CP_COMMIT();           // unconditional: keeps the wait_group invariant
        compute(c % 3);
    }

    // ---- epilogue ----
    #pragma unroll
    for (int mi = 0; mi < 2; mi++) {
        #pragma unroll
        for (int t = 0; t < 8; t++) {
            int gmA = m0 + wm * 32 + mi * 16 + (lane >> 2);
            int gn  = n0 + wn * 64 + t * 8 + ((lane & 3) << 1);
            #pragma unroll
            for (int half = 0; half < 2; half++) {
                int gm = gmA + half * 8;
                #pragma unroll
                for (int cc = 0; cc < 2; cc++) {
                    int g = gn + cc;
                    if (g < N) {
                        float v = acc[mi][t][half * 2 + cc] + bias[g];
                        if (GELU) v = 0.5f * v * (1.0f + erff(v * 0.70710678118654752f));
                        if (RES)  v += Rres[(size_t)gm * ldc + g];
                        if (TRIPLEOUT) {
                            __nv_bfloat16* o = (__nv_bfloat16*)Cout
                                             + ((size_t)gm * ldc + g) * 3;
                            __nv_bfloat162 sp = split1(v);
                            o[0] = sp.x; o[1] = sp.y; o[2] = sp.x;   // (h,l,h)
                        } else {
                            ((float*)Cout)[(size_t)gm * ldc + g] = v;
                        }
                    }
                }
            }
        }
    }
}

// ---------------------------------------------------------------------------
// HMMA flash attention (R8 champion compute; output -> triple bf16 ao3).
// ---------------------------------------------------------------------------
#define A3 200
#define A3B (A3 * 2)
#define ATILE (64 * A3B)
#define ASMEM (4 * ATILE)

__global__ __launch_bounds__(128, 2)
void attn_kernel(const float* __restrict__ qkv, __nv_bfloat16* __restrict__ og3)
{
    extern __shared__ __align__(16) char asm_[];
    char* sQ  = asm_;
    char* sK  = asm_ + ATILE;
    char* sP  = asm_ + 2 * ATILE;
    char* sVt = asm_ + 3 * ATILE;
    const uint32_t sQa = smem_u32(sQ), sKa = smem_u32(sK),
                   sPa = smem_u32(sP), sVta = smem_u32(sVt);

    const int bid = blockIdx.x;
    const int qb = 15 - (bid >> 4);
    const int bh = bid & 15;
    const int b = bh >> 3, h = bh & 7;
    const int tid = threadIdx.x;
    const int lane = tid & 31, w = tid >> 5;
    const int rowbase = b << 10;
    const int col0 = h << 6;
    const int lr = tid >> 1, lh = tid & 1;

    {
        const float* Qp = &qkv[(size_t)(rowbase + (qb << 6) + lr) * QKV_LD + col0 + lh * 32];
        char* dst = sQ + lr * A3B + lh * 192;
        #pragma unroll
        for (int gidx = 0; gidx < 8; gidx++) {
            float4 v = *(const float4*)(Qp + gidx * 4);
            const float vv[4] = {v.x, v.y, v.z, v.w};
            union { __nv_bfloat16 hh[12]; uint2 u[3]; } P;
            #pragma unroll
            for (int e = 0; e < 4; e++) {
                __nv_bfloat162 sp = split1(vv[e]);
                P.hh[e*3+0] = sp.x; P.hh[e*3+1] = sp.y; P.hh[e*3+2] = sp.x;
            }
            uint2* q2 = (uint2*)(dst + gidx * 24);
            q2[0] = P.u[0]; q2[1] = P.u[1]; q2[2] = P.u[2];
        }
    }

    float m0r = -3e38f, m1r = -3e38f, l0r = 0.0f, l1r = 0.0f;
    float Oacc[8][4];
    #pragma unroll
    for (int t = 0; t < 8; t++)
        #pragma unroll
        for (int k = 0; k < 4; k++) Oacc[t][k] = 0.0f;

    const int qrow0 = (qb << 6) + w * 16 + (lane >> 2);

    for (int kb = 0; kb <= qb; kb++) {
        __syncthreads();

        {
            const float* Kp = &qkv[(size_t)(rowbase + (kb << 6) + lr) * QKV_LD + col0 + DMODEL + lh * 32];
            char* dst = sK + lr * A3B + lh * 192;
            #pragma unroll
            for (int gidx = 0; gidx < 8; gidx++) {
                float4 v = *(const float4*)(Kp + gidx * 4);
                const float vv[4] = {v.x, v.y, v.z, v.w};
                union { __nv_bfloat16 hh[12]; uint2 u[3]; } P;
                #pragma unroll
                for (int e = 0; e < 4; e++) {
                    __nv_bfloat162 sp = split1(vv[e]);
                    P.hh[e*3+0] = sp.x; P.hh[e*3+1] = sp.x; P.hh[e*3+2] = sp.y;
                }
                uint2* q2 = (uint2*)(dst + gidx * 24);
                q2[0] = P.u[0]; q2[1] = P.u[1]; q2[2] = P.u[2];
            }
        }
        {
            const float* Vb = &qkv[(size_t)(rowbase + (kb << 6)) * QKV_LD + col0 + 2 * DMODEL + lr];
            char* dst = sVt + lr * A3B + lh * 192;
            #pragma unroll
            for (int gidx = 0; gidx < 8; gidx++) {
                union { __nv_bfloat16 hh[12]; uint2 u[3]; } P;
                #pragma unroll
                for (int e = 0; e < 4; e++) {
                    float v = Vb[(size_t)(lh * 32 + gidx * 4 + e) * QKV_LD];
                    __nv_bfloat162 sp = split1(v);
                    P.hh[e*3+0] = sp.x; P.hh[e*3+1] = sp.x; P.hh[e*3+2] = sp.y;
                }
                uint2* q2 = (uint2*)(dst + gidx * 24);
                q2[0] = P.u[0]; q2[1] = P.u[1]; q2[2] = P.u[2];
            }
        }
        __syncthreads();

        float S[8][4];
        #pragma unroll
        for (int t = 0; t < 8; t++)
            #pragma unroll
            for (int k = 0; k < 4; k++) S[t][k] = 0.0f;

        #pragma unroll
        for (int ks = 0; ks < 12; ks++) {
            uint32_t afrag[4];
            ldsm4(afrag, sQa + (w * 16 + (lane & 15)) * A3B + ks * 32 + ((lane >> 4) << 4));
            uint32_t bfrag[4][4];
            #pragma unroll
            for (int nt = 0; nt < 4; nt++) {
                int brow = nt * 16 + (lane & 7) + ((lane >> 4) << 3);
                ldsm4(bfrag[nt], sKa + brow * A3B + ks * 32 + (((lane >> 3) & 1) << 4));
            }
            #pragma unroll
            for (int t = 0; t < 8; t++)
                mma16816(S[t], afrag, &bfrag[t >> 1][(t & 1) * 2]);
        }

        const bool diag = (kb == qb);
        #pragma unroll
        for (int t = 0; t < 8; t++) {
            int cbase = t * 8 + ((lane & 3) << 1);
            #pragma unroll
            for (int cc = 0; cc < 2; cc++) {
                S[t][cc]     *= 0.125f;
                S[t][2 + cc] *= 0.125f;
                if (diag) {
                    int cl = cbase + cc;
                    if (cl > (w * 16 + (lane >> 2)))     S[t][cc]     = -3e38f;
                    if (cl > (w * 16 + (lane >> 2) + 8)) S[t][2 + cc] = -3e38f;
                }
            }
        }

        float c0 = -3e38f, c1 = -3e38f;
        #pragma unroll
        for (int t = 0; t < 8; t++) {
            c0 = fmaxf(c0, fmaxf(S[t][0], S[t][1]));
            c1 = fmaxf(c1, fmaxf(S[t][2], S[t][3]));
        }
        c0 = fmaxf(c0, __shfl_xor_sync(0xffffffffu, c0, 1));
        c0 = fmaxf(c0, __shfl_xor_sync(0xffffffffu, c0, 2));
        c1 = fmaxf(c1, __shfl_xor_sync(0xffffffffu, c1, 1));
        c1 = fmaxf(c1, __shfl_xor_sync(0xffffffffu, c1, 2));

        float nm0 = fmaxf(m0r, c0), nm1 = fmaxf(m1r, c1);
        float al0 = __expf(m0r - nm0), al1 = __expf(m1r - nm1);
        m0r = nm0; m1r = nm1;

        float s0 = 0.0f, s1 = 0.0f;
        #pragma unroll
        for (int t = 0; t < 8; t++) {
            #pragma unroll
            for (int cc = 0; cc < 2; cc++) {
                float p0 = __expf(S[t][cc]     - nm0);
                float p1 = __expf(S[t][2 + cc] - nm1);
                S[t][cc] = p0; S[t][2 + cc] = p1;
                s0 += p0; s1 += p1;
            }
        }
        s0 += __shfl_xor_sync(0xffffffffu, s0, 1);
        s0 += __shfl_xor_sync(0xffffffffu, s0, 2);
        s1 += __shfl_xor_sync(0xffffffffu, s1, 1);
        s1 += __shfl_xor_sync(0xffffffffu, s1, 2);
        l0r = l0r * al0 + s0;
        l1r = l1r * al1 + s1;

        #pragma unroll
        for (int t = 0; t < 8; t++) {
            Oacc[t][0] *= al0; Oacc[t][1] *= al0;
            Oacc[t][2] *= al1; Oacc[t][3] *= al1;
        }

        {
            int r0 = w * 16 + (lane >> 2);
            #pragma unroll
            for (int t = 0; t < 8; t++) {
                int cbyte = (t * 8 + ((lane & 3) << 1)) * 6;
                #pragma unroll
                for (int half = 0; half < 2; half++) {
                    __nv_bfloat162 pa = split1(S[t][half * 2 + 0]);
                    __nv_bfloat162 pb = split1(S[t][half * 2 + 1]);
                    uint32_t* dst = (uint32_t*)(sP + (r0 + half * 8) * A3B + cbyte);
                    dst[0] = pack2(pa.x, pa.y);
                    dst[1] = pack2(pa.x, pb.x);
                    dst[2] = pack2(pb.y, pb.x);
                }
            }
        }
        __syncthreads();

        #pragma unroll
        for (int ks = 0; ks < 12; ks++) {
            uint32_t afrag[4];
            ldsm4(afrag, sPa + (w * 16 + (lane & 15)) * A3B + ks * 32 + ((lane >> 4) << 4));
            uint32_t bfrag[4][4];
            #pragma unroll
            for (int nt = 0; nt < 4; nt++) {
                int brow = nt * 16 + (lane & 7) + ((lane >> 4) << 3);
                ldsm4(bfrag[nt], sVta + brow * A3B + ks * 32 + (((lane >> 3) & 1) << 4));
            }
            #pragma unroll
            for (int t = 0; t < 8; t++)
                mma16816(Oacc[t], afrag, &bfrag[t >> 1][(t & 1) * 2]);
        }
    }

    // final: O/l -> triple bf16 (h,l,h) into ao3
    float inv0 = 1.0f / l0r, inv1 = 1.0f / l1r;
    #pragma unroll
    for (int t = 0; t < 8; t++) {
        int colg = col0 + t * 8 + ((lane & 3) << 1);
        #pragma unroll
        for (int half = 0; half < 2; half++) {
            float inv = half ? inv1 : inv0;
            int grow = rowbase + qrow0 + half * 8;
            __nv_bfloat162 pa = split1(Oacc[t][half * 2 + 0] * inv);
            __nv_bfloat162 pb = split1(Oacc[t][half * 2 + 1] * inv);
            uint32_t* dst = (uint32_t*)(og3 + (size_t)grow * K3_D + (size_t)colg * 3);
            dst[0] = pack2(pa.x, pa.y);
            dst[1] = pack2(pa.x, pb.x);
            dst[2] = pack2(pb.y, pb.x);
        }
    }
}

// ---------------------------------------------------------------------------
// Host launcher (graph-capturable).
// ---------------------------------------------------------------------------
extern "C" void kernel_launch(void* const* d_in, const int* in_sizes, int n_in,
                              void* d_out, int out_size)
{
    const int*   tokens = (const int*)  d_in[0];
    const float* emb    = (const float*)d_in[1];
    const float* pos    = (const float*)d_in[2];
    const float* Wq     = (const float*)d_in[3];
    const float* bq     = (const float*)d_in[4];
    const float* Wk     = (const float*)d_in[5];
    const float* bk     = (const float*)d_in[6];
    const float* Wv     = (const float*)d_in[7];
    const float* bv     = (const float*)d_in[8];
    const float* Wo     = (const float*)d_in[9];
    const float* bo     = (const float*)d_in[10];
    const float* ln1g   = (const float*)d_in[11];
    const float* ln1b   = (const float*)d_in[12];
    const float* W1     = (const float*)d_in[13];
    const float* b1     = (const float*)d_in[14];
    const float* W2     = (const float*)d_in[15];
    const float* b2     = (const float*)d_in[16];
    const float* ln2g   = (const float*)d_in[17];
    const float* ln2b   = (const float*)d_in[18];
    const float* lnfg   = (const float*)d_in[19];
    const float* lnfb   = (const float*)d_in[20];
    const float* Whead  = (const float*)d_in[21];
    const float* bhead  = (const float*)d_in[22];
    float* out = (float*)d_out;

    float *x, *qkv, *bqkv;
    __nv_bfloat16 *h3, *ao3, *ff3, *wqkv3, *wo3, *w13, *w23, *wh3;
    cudaGetSymbolAddress((void**)&x,     g_x);
    cudaGetSymbolAddress((void**)&qkv,   g_qkv);
    cudaGetSymbolAddress((void**)&bqkv,  g_bqkv);
    cudaGetSymbolAddress((void**)&h3,    g_h3);
    cudaGetSymbolAddress((void**)&ao3,   g_ao3);
    cudaGetSymbolAddress((void**)&ff3,   g_ff3);
    cudaGetSymbolAddress((void**)&wqkv3, g_wqkv3);
    cudaGetSymbolAddress((void**)&wo3,   g_wo3);
    cudaGetSymbolAddress((void**)&w13,   g_w13);
    cudaGetSymbolAddress((void**)&w23,   g_w23);
    cudaGetSymbolAddress((void**)&wh3,   g_wh3);

    cudaFuncSetAttribute(attn_kernel, cudaFuncAttributeMaxDynamicSharedMemorySize, ASMEM);
    cudaFuncSetAttribute(hmma_gemm<false,false,false,false>, cudaFuncAttributeMaxDynamicSharedMemorySize, GSMEM);
    cudaFuncSetAttribute(hmma_gemm<false,true ,false,false>, cudaFuncAttributeMaxDynamicSharedMemorySize, GSMEM);
    cudaFuncSetAttribute(hmma_gemm<true ,false,true ,false>, cudaFuncAttributeMaxDynamicSharedMemorySize, GSMEM);
    cudaFuncSetAttribute(hmma_gemm<false,false,false,true >, cudaFuncAttributeMaxDynamicSharedMemorySize, GSMEM);

    const size_t DD = (size_t)DMODEL * DMODEL;
    const size_t FD = (size_t)DFF * DMODEL;

    // ---- per-launch weight pre-split to (h,h,l) triple bf16 ----
    auto wsplit = [](const float* s, __nv_bfloat16* d, size_t n) {
        long n8 = (long)(n / 8);
        wsplit3_kernel<<<(unsigned)((n8 + 255) / 256), 256>>>(s, d, n8);
    };
    for (int l = 0; l < NLAYER; l++) {
        const size_t vD = (size_t)l * DMODEL;
        wsplit(Wq + l * DD, wqkv3 + (size_t)l * QKV_LD * K3_D + (size_t)0    * K3_D, DD);
        wsplit(Wk + l * DD, wqkv3 + (size_t)l * QKV_LD * K3_D + (size_t)512  * K3_D, DD);
        wsplit(Wv + l * DD, wqkv3 + (size_t)l * QKV_LD * K3_D + (size_t)1024 * K3_D, DD);
        wsplit(Wo + l * DD, wo3   + (size_t)l * DMODEL * K3_D, DD);
        wsplit(W1 + l * FD, w13   + (size_t)l * DFF    * K3_D, FD);
        wsplit(W2 + l * FD, w23   + (size_t)l * DMODEL * K3_F, FD);
        cudaMemcpyAsync(bqkv + l * QKV_LD +          0, bq + vD, DMODEL * 4, cudaMemcpyDeviceToDevice);
        cudaMemcpyAsync(bqkv + l * QKV_LD +     DMODEL, bk + vD, DMODEL * 4, cudaMemcpyDeviceToDevice);
        cudaMemcpyAsync(bqkv + l * QKV_LD + 2 * DMODEL, bv + vD, DMODEL * 4, cudaMemcpyDeviceToDevice);
    }
    wsplit(Whead, wh3, (size_t)VOCAB * DMODEL);

    embed_kernel<<<NROWS, 128>>>(tokens, emb, pos, x);

    const dim3 gQKV(QKV_LD / 128, NROWS / 128);
    const dim3 gD  (DMODEL / 128, NROWS / 128);
    const dim3 gF  (DFF / 128,    NROWS / 128);
    const dim3 gV  (NROWS / 128, (VOCAB + 127) / 128);   // SWAP: m fastest

    for (int l = 0; l < NLAYER; l++) {
        const size_t vD = (size_t)l * DMODEL;

        ln_kernel<<<NROWS, 128>>>(x, ln1g + vD, ln1b + vD, h3);
        hmma_gemm<false,false,false,false><<<gQKV, 256, GSMEM>>>(
            h3, wqkv3 + (size_t)l * QKV_LD * K3_D, bqkv + l * QKV_LD, nullptr,
            qkv, QKV_LD, K3_D, QKV_LD);
        attn_kernel<<<256, 128, ASMEM>>>(qkv, ao3);
        hmma_gemm<false,true,false,false><<<gD, 256, GSMEM>>>(
            ao3, wo3 + (size_t)l * DMODEL * K3_D, bo + vD, x, x, DMODEL, K3_D, DMODEL);

        ln_kernel<<<NROWS, 128>>>(x, ln2g + vD, ln2b + vD, h3);
        hmma_gemm<true,false,true,false><<<gF, 256, GSMEM>>>(
            h3, w13 + (size_t)l * DFF * K3_D, b1 + (size_t)l * DFF, nullptr,
            ff3, DFF, K3_D, DFF);
        hmma_gemm<false,true,false,false><<<gD, 256, GSMEM>>>(
            ff3, w23 + (size_t)l * DMODEL * K3_F, b2 + vD, x, x, DMODEL, K3_F, DMODEL);
    }

    ln_kernel<<<NROWS, 128>>>(x, lnfg, lnfb, h3);
    hmma_gemm<false,false,false,true><<<gV, 256, GSMEM>>>(
        h3, wh3, bhead, nullptr, out, VOCAB, K3_D, VOCAB);
}

// round 17
// speedup vs baseline: 1.4801x; 1.4801x over previous
#include <cuda_runtime.h>
#include <cuda_bf16.h>
#include <math.h>
#include <stdint.h>

// ---------------------------------------------------------------------------
// ManifoldTransformer on GB300.
// Layers: mma.sync bf16 + 3-term hi/lo split (fp32-class accuracy), R8/R13
// champion GEMM + HMMA flash attention.
// Head GEMM (logits only): single-pass tf32 mma m16n8k8 (error ~2e-4, no
// compounding) -> 33% less tensor work + half the operand traffic.
// B=2,S=1024,D=512,H=8,DFF=2048,L=4,V=50257.
// ---------------------------------------------------------------------------

#define NROWS 2048
#define DMODEL 512
#define DFF 2048
#define NLAYER 4
#define VOCAB 50257
#define SEQ 1024
#define QKV_LD 1536

// ---------------- scratch (device globals: allocation-free) -----------------
__device__ __align__(256) float g_x  [NROWS * DMODEL];
__device__ __align__(256) float g_h  [NROWS * DMODEL];
__device__ __align__(256) float g_ao [NROWS * DMODEL];
__device__ __align__(256) float g_ff [NROWS * DFF];
__device__ __align__(256) float g_qkv[NROWS * QKV_LD];
__device__ __align__(256) float g_wqkvf[QKV_LD * DMODEL];
__device__ __align__(256) float g_bqkv [QKV_LD];

// ---------------- helpers ----------------------------------------------------
__device__ __forceinline__ uint32_t smem_u32(const void* p) {
    uint32_t a;
    asm("{ .reg .u64 t; cvta.to.shared.u64 t, %1; cvt.u32.u64 %0, t; }"
        : "=r"(a) : "l"(p));
    return a;
}
__device__ __forceinline__ void ldsm4(uint32_t* r, uint32_t addr) {
    asm volatile("ldmatrix.sync.aligned.m8n8.x4.shared.b16 {%0,%1,%2,%3}, [%4];"
        : "=r"(r[0]), "=r"(r[1]), "=r"(r[2]), "=r"(r[3]) : "r"(addr));
}
__device__ __forceinline__ void mma16816(float* d, const uint32_t* a, const uint32_t* b) {
    asm volatile("mma.sync.aligned.m16n8k16.row.col.f32.bf16.bf16.f32 "
        "{%0,%1,%2,%3}, {%4,%5,%6,%7}, {%8,%9}, {%0,%1,%2,%3};"
        : "+f"(d[0]), "+f"(d[1]), "+f"(d[2]), "+f"(d[3])
        : "r"(a[0]), "r"(a[1]), "r"(a[2]), "r"(a[3]), "r"(b[0]), "r"(b[1]));
}
__device__ __forceinline__ void mma1688tf(float* d, const uint32_t* a, const uint32_t* b) {
    asm volatile("mma.sync.aligned.m16n8k8.row.col.f32.tf32.tf32.f32 "
        "{%0,%1,%2,%3}, {%4,%5,%6,%7}, {%8,%9}, {%0,%1,%2,%3};"
        : "+f"(d[0]), "+f"(d[1]), "+f"(d[2]), "+f"(d[3])
        : "r"(a[0]), "r"(a[1]), "r"(a[2]), "r"(a[3]), "r"(b[0]), "r"(b[1]));
}
__device__ __forceinline__ uint32_t f2tf32(float x) {
    uint32_t t;
    asm("cvt.rna.tf32.f32 %0, %1;" : "=r"(t) : "f"(x));
    return t;
}
__device__ __forceinline__ __nv_bfloat162 split1(float x) {
    __nv_bfloat162 r;
    r.x = __float2bfloat16(x);
    r.y = __float2bfloat16(x - __bfloat162float(r.x));
    return r;
}
__device__ __forceinline__ uint32_t pack2(__nv_bfloat16 a, __nv_bfloat16 b) {
    __nv_bfloat162 t; t.x = a; t.y = b;
    return *(uint32_t*)&t;
}

// ---------------- embedding -------------------------------------------------
__global__ void embed_kernel(const int* __restrict__ tok,
                             const float* __restrict__ emb,
                             const float* __restrict__ pos,
                             float* __restrict__ x)
{
    int row = blockIdx.x, tid = threadIdx.x;
    int t = tok[row], s = row & (SEQ - 1);
    float4 e = *(const float4*)&emb[(size_t)t * DMODEL + tid * 4];
    float4 p = *(const float4*)&pos[(size_t)s * DMODEL + tid * 4];
    e.x += p.x; e.y += p.y; e.z += p.z; e.w += p.w;
    *(float4*)&x[(size_t)row * DMODEL + tid * 4] = e;
}

// ---------------- LayerNorm (fp32 out) ---------------------------------------
__global__ void ln_kernel(const float* __restrict__ x,
                          const float* __restrict__ g,
                          const float* __restrict__ b,
                          float* __restrict__ y)
{
    __shared__ float red[4];
    __shared__ float bc;
    int row = blockIdx.x, tid = threadIdx.x;
    int lane = tid & 31, w = tid >> 5;

    float4 v = *(const float4*)&x[(size_t)row * DMODEL + tid * 4];
    float s = v.x + v.y + v.z + v.w;
    #pragma unroll
    for (int o = 16; o; o >>= 1) s += __shfl_xor_sync(0xffffffffu, s, o);
    if (lane == 0) red[w] = s;
    __syncthreads();
    if (tid == 0) bc = (red[0] + red[1] + red[2] + red[3]) * (1.0f / 512.0f);
    __syncthreads();
    float mean = bc;
    float dx = v.x - mean, dy = v.y - mean, dz = v.z - mean, dw = v.w - mean;
    float s2 = dx*dx + dy*dy + dz*dz + dw*dw;
    #pragma unroll
    for (int o = 16; o; o >>= 1) s2 += __shfl_xor_sync(0xffffffffu, s2, o);
    __syncthreads();
    if (lane == 0) red[w] = s2;
    __syncthreads();
    if (tid == 0) bc = rsqrtf((red[0] + red[1] + red[2] + red[3]) * (1.0f / 512.0f) + 1e-5f);
    __syncthreads();
    float inv = bc;

    float4 gg = *(const float4*)&g[tid * 4];
    float4 bb = *(const float4*)&b[tid * 4];
    float4 o4;
    o4.x = dx * inv * gg.x + bb.x;
    o4.y = dy * inv * gg.y + bb.y;
    o4.z = dz * inv * gg.z + bb.z;
    o4.w = dw * inv * gg.w + bb.w;
    *(float4*)&y[(size_t)row * DMODEL + tid * 4] = o4;
}

// ---------------------------------------------------------------------------
// HMMA GEMM with fused fp32->triple-bf16 split in the loaders. (R8 champion)
// ---------------------------------------------------------------------------
#define SROW 112
#define TILE (128 * SROW)
#define STAGE (2 * TILE)
#define GSMEM (3 * STAGE)

template<bool GELU, bool RES>
__global__ __launch_bounds__(256, 2)
void hmma_gemm(const float* __restrict__ A, const float* __restrict__ Bm,
               const float* __restrict__ bias, const float* __restrict__ Rres,
               float* __restrict__ C, int N, int K, int ldc)
{
    extern __shared__ __align__(16) char sm[];

    const int tid = threadIdx.x;
    const int lane = tid & 31, wid = tid >> 5;
    const int wm = wid & 3, wn = wid >> 2;
    const int m0 = blockIdx.y << 7, n0 = blockIdx.x << 7;
    const int lrow = tid >> 1, lhalf = tid & 1;

    float acc[2][8][4];
    #pragma unroll
    for (int i = 0; i < 2; i++)
        #pragma unroll
        for (int j = 0; j < 8; j++)
            #pragma unroll
            for (int k = 0; k < 4; k++) acc[i][j][k] = 0.0f;

    const int nc = K >> 4;
    float a_st[8], b_st[8];
    const bool bvalid = (n0 + lrow < N);

    auto ldg = [&](int c) {
        const float* Ap = A + (size_t)(m0 + lrow) * K + c * 16 + lhalf * 8;
        *(float4*)(a_st)     = *(const float4*)(Ap);
        *(float4*)(a_st + 4) = *(const float4*)(Ap + 4);
        if (bvalid) {
            const float* Bp = Bm + (size_t)(n0 + lrow) * K + c * 16 + lhalf * 8;
            *(float4*)(b_st)     = *(const float4*)(Bp);
            *(float4*)(b_st + 4) = *(const float4*)(Bp + 4);
        } else {
            #pragma unroll
            for (int e = 0; e < 8; e++) b_st[e] = 0.0f;
        }
    };
    auto sts = [&](int stage) {
        char* sA = sm + stage * STAGE;
        char* sB = sA + TILE;
        const int base = lrow * SROW + lhalf * 48;
        union { __nv_bfloat16 h[24]; uint4 u[3]; } P;
        #pragma unroll
        for (int e = 0; e < 8; e++) {
            __nv_bfloat162 sp = split1(a_st[e]);
            P.h[e * 3 + 0] = sp.x;
            P.h[e * 3 + 1] = sp.y;
            P.h[e * 3 + 2] = sp.x;
        }
        #pragma unroll
        for (int i = 0; i < 3; i++) ((uint4*)(sA + base))[i] = P.u[i];
        #pragma unroll
        for (int e = 0; e < 8; e++) {
            __nv_bfloat162 sp = split1(b_st[e]);
            P.h[e * 3 + 0] = sp.x;
            P.h[e * 3 + 1] = sp.x;
            P.h[e * 3 + 2] = sp.y;
        }
        #pragma unroll
        for (int i = 0; i < 3; i++) ((uint4*)(sB + base))[i] = P.u[i];
    };
    auto compute = [&](int stage) {
        uint32_t aBase = smem_u32(sm + stage * STAGE);
        uint32_t bBase = aBase + TILE;
        #pragma unroll
        for (int ks = 0; ks < 3; ks++) {
            uint32_t afrag[2][4];
            #pragma unroll
            for (int mi = 0; mi < 2; mi++) {
                int arow = wm * 32 + mi * 16 + (lane & 15);
                int abyte = ks * 32 + ((lane >> 4) << 4);
                ldsm4(afrag[mi], aBase + arow * SROW + abyte);
            }
            uint32_t bfrag[4][4];
            #pragma unroll
            for (int ni = 0; ni < 4; ni++) {
                int brow = wn * 64 + ni * 16 + (lane & 7) + ((lane >> 4) << 3);
                int bbyte = ks * 32 + (((lane >> 3) & 1) << 4);
                ldsm4(bfrag[ni], bBase + brow * SROW + bbyte);
            }
            #pragma unroll
            for (int mi = 0; mi < 2; mi++)
                #pragma unroll
                for (int t = 0; t < 8; t++)
                    mma16816(acc[mi][t], afrag[mi], &bfrag[t >> 1][(t & 1) * 2]);
        }
    };

    ldg(0);
    sts(0);
    if (nc > 1) ldg(1);
    __syncthreads();
    for (int c = 0; c < nc; c++) {
        if (c + 1 < nc) sts((c + 1) % 3);
        if (c + 2 < nc) ldg(c + 2);
        compute(c % 3);
        __syncthreads();
    }

    #pragma unroll
    for (int mi = 0; mi < 2; mi++) {
        #pragma unroll
        for (int t = 0; t < 8; t++) {
            int gmA = m0 + wm * 32 + mi * 16 + (lane >> 2);
            int gn  = n0 + wn * 64 + t * 8 + ((lane & 3) << 1);
            #pragma unroll
            for (int half = 0; half < 2; half++) {
                int gm = gmA + half * 8;
                #pragma unroll
                for (int cc = 0; cc < 2; cc++) {
                    int g = gn + cc;
                    if (g < N) {
                        float v = acc[mi][t][half * 2 + cc] + bias[g];
                        if (GELU) v = 0.5f * v * (1.0f + erff(v * 0.70710678118654752f));
                        if (RES)  v += Rres[(size_t)gm * ldc + g];
                        C[(size_t)gm * ldc + g] = v;
                    }
                }
            }
        }
    }
}

// ---------------------------------------------------------------------------
// tf32 GEMM for the head: C[M,N] = A[M,K] @ B[N,K]^T + bias, single-pass tf32.
// CTA 128x128, BK=16 fp32 (2 k8-steps), 3-stage ring, smem row 20 floats
// (conflict-free scalar LDS for both fragments). Grid: m fastest (L2).
// ---------------------------------------------------------------------------
#define TROW 20
#define TTILE (128 * TROW * 4)     // 10240 B
#define TSTAGE (2 * TTILE)         // 20480 B
#define TSMEM (3 * TSTAGE)         // 61440 B

__global__ __launch_bounds__(256, 2)
void tf32_gemm(const float* __restrict__ A, const float* __restrict__ Bm,
               const float* __restrict__ bias, float* __restrict__ C,
               int N, int K, int ldc)
{
    extern __shared__ __align__(16) char sm[];
    const uint32_t smbase = smem_u32(sm);

    const int tid = threadIdx.x;
    const int lane = tid & 31, wid = tid >> 5;
    const int wm = wid & 3, wn = wid >> 2;
    const int m0 = blockIdx.x << 7;        // m fastest
    const int n0 = blockIdx.y << 7;
    const int lrow = tid >> 1, lhalf = tid & 1;

    float acc[2][8][4];
    #pragma unroll
    for (int i = 0; i < 2; i++)
        #pragma unroll
        for (int j = 0; j < 8; j++)
            #pragma unroll
            for (int k = 0; k < 4; k++) acc[i][j][k] = 0.0f;

    const int nc = K >> 4;                 // 32
    float a_st[8], b_st[8];
    const bool bvalid = (n0 + lrow < N);

    auto ldg = [&](int c) {
        const float* Ap = A + (size_t)(m0 + lrow) * K + c * 16 + lhalf * 8;
        *(float4*)(a_st)     = *(const float4*)(Ap);
        *(float4*)(a_st + 4) = *(const float4*)(Ap + 4);
        if (bvalid) {
            const float* Bp = Bm + (size_t)(n0 + lrow) * K + c * 16 + lhalf * 8;
            *(float4*)(b_st)     = *(const float4*)(Bp);
            *(float4*)(b_st + 4) = *(const float4*)(Bp + 4);
        } else {
            #pragma unroll
            for (int e = 0; e < 8; e++) b_st[e] = 0.0f;
        }
    };
    auto sts = [&](int stage) {
        uint32_t sA = smbase + stage * TSTAGE;
        uint32_t sB = sA + TTILE;
        const uint32_t off = (lrow * TROW + lhalf * 8) * 4;
        uint4 u;
        u.x = f2tf32(a_st[0]); u.y = f2tf32(a_st[1]);
        u.z = f2tf32(a_st[2]); u.w = f2tf32(a_st[3]);
        *(uint4*)(sm + (sA - smbase) + off) = u;
        u.x = f2tf32(a_st[4]); u.y = f2tf32(a_st[5]);
        u.z = f2tf32(a_st[6]); u.w = f2tf32(a_st[7]);
        *(uint4*)(sm + (sA - smbase) + off + 16) = u;
        u.x = f2tf32(b_st[0]); u.y = f2tf32(b_st[1]);
        u.z = f2tf32(b_st[2]); u.w = f2tf32(b_st[3]);
        *(uint4*)(sm + (sB - smbase) + off) = u;
        u.x = f2tf32(b_st[4]); u.y = f2tf32(b_st[5]);
        u.z = f2tf32(b_st[6]); u.w = f2tf32(b_st[7]);
        *(uint4*)(sm + (sB - smbase) + off + 16) = u;
    };
    auto compute = [&](int stage) {
        const uint32_t* sA = (const uint32_t*)(sm + stage * TSTAGE);
        const uint32_t* sB = (const uint32_t*)(sm + stage * TSTAGE + TTILE);
        #pragma unroll
        for (int ks = 0; ks < 2; ks++) {
            const int k0 = ks * 8 + (lane & 3);
            uint32_t af[2][4];
            #pragma unroll
            for (int mi = 0; mi < 2; mi++) {
                int r0 = wm * 32 + mi * 16 + (lane >> 2);
                af[mi][0] = sA[r0 * TROW + k0];
                af[mi][1] = sA[(r0 + 8) * TROW + k0];
                af[mi][2] = sA[r0 * TROW + k0 + 4];
                af[mi][3] = sA[(r0 + 8) * TROW + k0 + 4];
            }
            #pragma unroll
            for (int nt = 0; nt < 8; nt++) {
                int c0 = wn * 64 + nt * 8 + (lane >> 2);
                uint32_t bf[2];
                bf[0] = sB[c0 * TROW + k0];
                bf[1] = sB[c0 * TROW + k0 + 4];
                #pragma unroll
                for (int mi = 0; mi < 2; mi++)
                    mma1688tf(acc[mi][nt], af[mi], bf);
            }
        }
    };

    ldg(0);
    sts(0);
    if (nc > 1) ldg(1);
    __syncthreads();
    for (int c = 0; c < nc; c++) {
        if (c + 1 < nc) sts((c + 1) % 3);
        if (c + 2 < nc) ldg(c + 2);
        compute(c % 3);
        __syncthreads();
    }

    #pragma unroll
    for (int mi = 0; mi < 2; mi++) {
        #pragma unroll
        for (int t = 0; t < 8; t++) {
            int gmA = m0 + wm * 32 + mi * 16 + (lane >> 2);
            int gn  = n0 + wn * 64 + t * 8 + ((lane & 3) << 1);
            #pragma unroll
            for (int half = 0; half < 2; half++) {
                int gm = gmA + half * 8;
                #pragma unroll
                for (int cc = 0; cc < 2; cc++) {
                    int g = gn + cc;
                    if (g < N) {
                        C[(size_t)gm * ldc + g] = acc[mi][t][half * 2 + cc] + bias[g];
                    }
                }
            }
        }
    }
}

// ---------------------------------------------------------------------------
// HMMA flash attention (R8 champion, byte-identical).
// ---------------------------------------------------------------------------
#define A3 200
#define A3B (A3 * 2)
#define ATILE (64 * A3B)
#define ASMEM (4 * ATILE)

__global__ __launch_bounds__(128, 2)
void attn_kernel(const float* __restrict__ qkv, float* __restrict__ og)
{
    extern __shared__ __align__(16) char asm_[];
    char* sQ  = asm_;
    char* sK  = asm_ + ATILE;
    char* sP  = asm_ + 2 * ATILE;
    char* sVt = asm_ + 3 * ATILE;
    const uint32_t sQa = smem_u32(sQ), sKa = smem_u32(sK),
                   sPa = smem_u32(sP), sVta = smem_u32(sVt);

    const int bid = blockIdx.x;
    const int qb = 15 - (bid >> 4);
    const int bh = bid & 15;
    const int b = bh >> 3, h = bh & 7;
    const int tid = threadIdx.x;
    const int lane = tid & 31, w = tid >> 5;
    const int rowbase = b << 10;
    const int col0 = h << 6;
    const int lr = tid >> 1, lh = tid & 1;

    {
        const float* Qp = &qkv[(size_t)(rowbase + (qb << 6) + lr) * QKV_LD + col0 + lh * 32];
        char* dst = sQ + lr * A3B + lh * 192;
        #pragma unroll
        for (int gidx = 0; gidx < 8; gidx++) {
            float4 v = *(const float4*)(Qp + gidx * 4);
            const float vv[4] = {v.x, v.y, v.z, v.w};
            union { __nv_bfloat16 hh[12]; uint2 u[3]; } P;
            #pragma unroll
            for (int e = 0; e < 4; e++) {
                __nv_bfloat162 sp = split1(vv[e]);
                P.hh[e*3+0] = sp.x; P.hh[e*3+1] = sp.y; P.hh[e*3+2] = sp.x;
            }
            uint2* q2 = (uint2*)(dst + gidx * 24);
            q2[0] = P.u[0]; q2[1] = P.u[1]; q2[2] = P.u[2];
        }
    }

    float m0r = -3e38f, m1r = -3e38f, l0r = 0.0f, l1r = 0.0f;
    float Oacc[8][4];
    #pragma unroll
    for (int t = 0; t < 8; t++)
        #pragma unroll
        for (int k = 0; k < 4; k++) Oacc[t][k] = 0.0f;

    const int qrow0 = (qb << 6) + w * 16 + (lane >> 2);

    for (int kb = 0; kb <= qb; kb++) {
        __syncthreads();

        {
            const float* Kp = &qkv[(size_t)(rowbase + (kb << 6) + lr) * QKV_LD + col0 + DMODEL + lh * 32];
            char* dst = sK + lr * A3B + lh * 192;
            #pragma unroll
            for (int gidx = 0; gidx < 8; gidx++) {
                float4 v = *(const float4*)(Kp + gidx * 4);
                const float vv[4] = {v.x, v.y, v.z, v.w};
                union { __nv_bfloat16 hh[12]; uint2 u[3]; } P;
                #pragma unroll
                for (int e = 0; e < 4; e++) {
                    __nv_bfloat162 sp = split1(vv[e]);
                    P.hh[e*3+0] = sp.x; P.hh[e*3+1] = sp.x; P.hh[e*3+2] = sp.y;
                }
                uint2* q2 = (uint2*)(dst + gidx * 24);
                q2[0] = P.u[0]; q2[1] = P.u[1]; q2[2] = P.u[2];
            }
        }
        {
            const float* Vb = &qkv[(size_t)(rowbase + (kb << 6)) * QKV_LD + col0 + 2 * DMODEL + lr];
            char* dst = sVt + lr * A3B + lh * 192;
            #pragma unroll
            for (int gidx = 0; gidx < 8; gidx++) {
                union { __nv_bfloat16 hh[12]; uint2 u[3]; } P;
                #pragma unroll
                for (int e = 0; e < 4; e++) {
                    float v = Vb[(size_t)(lh * 32 + gidx * 4 + e) * QKV_LD];
                    __nv_bfloat162 sp = split1(v);
                    P.hh[e*3+0] = sp.x; P.hh[e*3+1] = sp.x; P.hh[e*3+2] = sp.y;
                }
                uint2* q2 = (uint2*)(dst + gidx * 24);
                q2[0] = P.u[0]; q2[1] = P.u[1]; q2[2] = P.u[2];
            }
        }
        __syncthreads();

        float S[8][4];
        #pragma unroll
        for (int t = 0; t < 8; t++)
            #pragma unroll
            for (int k = 0; k < 4; k++) S[t][k] = 0.0f;

        #pragma unroll
        for (int ks = 0; ks < 12; ks++) {
            uint32_t afrag[4];
            ldsm4(afrag, sQa + (w * 16 + (lane & 15)) * A3B + ks * 32 + ((lane >> 4) << 4));
            uint32_t bfrag[4][4];
            #pragma unroll
            for (int nt = 0; nt < 4; nt++) {
                int brow = nt * 16 + (lane & 7) + ((lane >> 4) << 3);
                ldsm4(bfrag[nt], sKa + brow * A3B + ks * 32 + (((lane >> 3) & 1) << 4));
            }
            #pragma unroll
            for (int t = 0; t < 8; t++)
                mma16816(S[t], afrag, &bfrag[t >> 1][(t & 1) * 2]);
        }

        const bool diag = (kb == qb);
        #pragma unroll
        for (int t = 0; t < 8; t++) {
            int cbase = t * 8 + ((lane & 3) << 1);
            #pragma unroll
            for (int cc = 0; cc < 2; cc++) {
                S[t][cc]     *= 0.125f;
                S[t][2 + cc] *= 0.125f;
                if (diag) {
                    int cl = cbase + cc;
                    if (cl > (w * 16 + (lane >> 2)))     S[t][cc]     = -3e38f;
                    if (cl > (w * 16 + (lane >> 2) + 8)) S[t][2 + cc] = -3e38f;
                }
            }
        }

        float c0 = -3e38f, c1 = -3e38f;
        #pragma unroll
        for (int t = 0; t < 8; t++) {
            c0 = fmaxf(c0, fmaxf(S[t][0], S[t][1]));
            c1 = fmaxf(c1, fmaxf(S[t][2], S[t][3]));
        }
        c0 = fmaxf(c0, __shfl_xor_sync(0xffffffffu, c0, 1));
        c0 = fmaxf(c0, __shfl_xor_sync(0xffffffffu, c0, 2));
        c1 = fmaxf(c1, __shfl_xor_sync(0xffffffffu, c1, 1));
        c1 = fmaxf(c1, __shfl_xor_sync(0xffffffffu, c1, 2));

        float nm0 = fmaxf(m0r, c0), nm1 = fmaxf(m1r, c1);
        float al0 = __expf(m0r - nm0), al1 = __expf(m1r - nm1);
        m0r = nm0; m1r = nm1;

        float s0 = 0.0f, s1 = 0.0f;
        #pragma unroll
        for (int t = 0; t < 8; t++) {
            #pragma unroll
            for (int cc = 0; cc < 2; cc++) {
                float p0 = __expf(S[t][cc]     - nm0);
                float p1 = __expf(S[t][2 + cc] - nm1);
                S[t][cc] = p0; S[t][2 + cc] = p1;
                s0 += p0; s1 += p1;
            }
        }
        s0 += __shfl_xor_sync(0xffffffffu, s0, 1);
        s0 += __shfl_xor_sync(0xffffffffu, s0, 2);
        s1 += __shfl_xor_sync(0xffffffffu, s1, 1);
        s1 += __shfl_xor_sync(0xffffffffu, s1, 2);
        l0r = l0r * al0 + s0;
        l1r = l1r * al1 + s1;

        #pragma unroll
        for (int t = 0; t < 8; t++) {
            Oacc[t][0] *= al0; Oacc[t][1] *= al0;
            Oacc[t][2] *= al1; Oacc[t][3] *= al1;
        }

        {
            int r0 = w * 16 + (lane >> 2);
            #pragma unroll
            for (int t = 0; t < 8; t++) {
                int cbyte = (t * 8 + ((lane & 3) << 1)) * 6;
                #pragma unroll
                for (int half = 0; half < 2; half++) {
                    __nv_bfloat162 pa = split1(S[t][half * 2 + 0]);
                    __nv_bfloat162 pb = split1(S[t][half * 2 + 1]);
                    uint32_t* dst = (uint32_t*)(sP + (r0 + half * 8) * A3B + cbyte);
                    dst[0] = pack2(pa.x, pa.y);
                    dst[1] = pack2(pa.x, pb.x);
                    dst[2] = pack2(pb.y, pb.x);
                }
            }
        }
        __syncthreads();

        #pragma unroll
        for (int ks = 0; ks < 12; ks++) {
            uint32_t afrag[4];
            ldsm4(afrag, sPa + (w * 16 + (lane & 15)) * A3B + ks * 32 + ((lane >> 4) << 4));
            uint32_t bfrag[4][4];
            #pragma unroll
            for (int nt = 0; nt < 4; nt++) {
                int brow = nt * 16 + (lane & 7) + ((lane >> 4) << 3);
                ldsm4(bfrag[nt], sVta + brow * A3B + ks * 32 + (((lane >> 3) & 1) << 4));
            }
            #pragma unroll
            for (int t = 0; t < 8; t++)
                mma16816(Oacc[t], afrag, &bfrag[t >> 1][(t & 1) * 2]);
        }
    }

    float inv0 = 1.0f / l0r, inv1 = 1.0f / l1r;
    #pragma unroll
    for (int t = 0; t < 8; t++) {
        int gn = col0 + t * 8 + ((lane & 3) << 1);
        float2 v0 = make_float2(Oacc[t][0] * inv0, Oacc[t][1] * inv0);
        float2 v1 = make_float2(Oacc[t][2] * inv1, Oacc[t][3] * inv1);
        *(float2*)&og[(size_t)(rowbase + qrow0) * DMODEL + gn]     = v0;
        *(float2*)&og[(size_t)(rowbase + qrow0 + 8) * DMODEL + gn] = v1;
    }
}

// ---------------------------------------------------------------------------
// Host launcher (graph-capturable).
// ---------------------------------------------------------------------------
extern "C" void kernel_launch(void* const* d_in, const int* in_sizes, int n_in,
                              void* d_out, int out_size)
{
    const int*   tokens = (const int*)  d_in[0];
    const float* emb    = (const float*)d_in[1];
    const float* pos    = (const float*)d_in[2];
    const float* Wq     = (const float*)d_in[3];
    const float* bq     = (const float*)d_in[4];
    const float* Wk     = (const float*)d_in[5];
    const float* bk     = (const float*)d_in[6];
    const float* Wv     = (const float*)d_in[7];
    const float* bv     = (const float*)d_in[8];
    const float* Wo     = (const float*)d_in[9];
    const float* bo     = (const float*)d_in[10];
    const float* ln1g   = (const float*)d_in[11];
    const float* ln1b   = (const float*)d_in[12];
    const float* W1     = (const float*)d_in[13];
    const float* b1     = (const float*)d_in[14];
    const float* W2     = (const float*)d_in[15];
    const float* b2     = (const float*)d_in[16];
    const float* ln2g   = (const float*)d_in[17];
    const float* ln2b   = (const float*)d_in[18];
    const float* lnfg   = (const float*)d_in[19];
    const float* lnfb   = (const float*)d_in[20];
    const float* Whead  = (const float*)d_in[21];
    const float* bhead  = (const float*)d_in[22];
    float* out = (float*)d_out;

    float *x, *h, *ao, *ff, *qkv, *wqkvf, *bqkv;
    cudaGetSymbolAddress((void**)&x,     g_x);
    cudaGetSymbolAddress((void**)&h,     g_h);
    cudaGetSymbolAddress((void**)&ao,    g_ao);
    cudaGetSymbolAddress((void**)&ff,    g_ff);
    cudaGetSymbolAddress((void**)&qkv,   g_qkv);
    cudaGetSymbolAddress((void**)&wqkvf, g_wqkvf);
    cudaGetSymbolAddress((void**)&bqkv,  g_bqkv);

    cudaFuncSetAttribute(attn_kernel, cudaFuncAttributeMaxDynamicSharedMemorySize, ASMEM);
    cudaFuncSetAttribute(hmma_gemm<false,false>, cudaFuncAttributeMaxDynamicSharedMemorySize, GSMEM);
    cudaFuncSetAttribute(hmma_gemm<false,true >, cudaFuncAttributeMaxDynamicSharedMemorySize, GSMEM);
    cudaFuncSetAttribute(hmma_gemm<true ,false>, cudaFuncAttributeMaxDynamicSharedMemorySize, GSMEM);
    cudaFuncSetAttribute(tf32_gemm, cudaFuncAttributeMaxDynamicSharedMemorySize, TSMEM);

    embed_kernel<<<NROWS, 128>>>(tokens, emb, pos, x);

    const dim3 gQKV(QKV_LD / 128, NROWS / 128);
    const dim3 gD  (DMODEL / 128, NROWS / 128);
    const dim3 gF  (DFF / 128,    NROWS / 128);
    const dim3 gV  (NROWS / 128, (VOCAB + 127) / 128);   // m fastest

    const size_t DD = (size_t)DMODEL * DMODEL;
    const size_t FD = (size_t)DFF * DMODEL;

    for (int l = 0; l < NLAYER; l++) {
        const size_t vD = (size_t)l * DMODEL;

        cudaMemcpyAsync(wqkvf,            Wq + l * DD, DD * 4, cudaMemcpyDeviceToDevice);
        cudaMemcpyAsync(wqkvf + DD,       Wk + l * DD, DD * 4, cudaMemcpyDeviceToDevice);
        cudaMemcpyAsync(wqkvf + 2 * DD,   Wv + l * DD, DD * 4, cudaMemcpyDeviceToDevice);
        cudaMemcpyAsync(bqkv,             bq + vD, DMODEL * 4, cudaMemcpyDeviceToDevice);
        cudaMemcpyAsync(bqkv + DMODEL,    bk + vD, DMODEL * 4, cudaMemcpyDeviceToDevice);
        cudaMemcpyAsync(bqkv + 2*DMODEL,  bv + vD, DMODEL * 4, cudaMemcpyDeviceToDevice);

        ln_kernel<<<NROWS, 128>>>(x, ln1g + vD, ln1b + vD, h);
        hmma_gemm<false,false><<<gQKV, 256, GSMEM>>>(
            h, wqkvf, bqkv, nullptr, qkv, QKV_LD, DMODEL, QKV_LD);
        attn_kernel<<<256, 128, ASMEM>>>(qkv, ao);
        hmma_gemm<false,true><<<gD, 256, GSMEM>>>(
            ao, Wo + l * DD, bo + vD, x, x, DMODEL, DMODEL, DMODEL);

        ln_kernel<<<NROWS, 128>>>(x, ln2g + vD, ln2b + vD, h);
        hmma_gemm<true,false><<<gF, 256, GSMEM>>>(
            h, W1 + l * FD, b1 + (size_t)l * DFF, nullptr, ff, DFF, DMODEL, DFF);
        hmma_gemm<false,true><<<gD, 256, GSMEM>>>(
            ff, W2 + l * FD, b2 + vD, x, x, DMODEL, DFF, DMODEL);
    }

    ln_kernel<<<NROWS, 128>>>(x, lnfg, lnfb, h);
    tf32_gemm<<<gV, 256, TSMEM>>>(h, Whead, bhead, out, VOCAB, DMODEL, VOCAB);
}